// round 14
// baseline (speedup 1.0000x reference)
#include <cuda_runtime.h>
#include <cstdint>

// out[t,:] = 1 / where(dmat[row(t),:]==0, BIG, dmat[row(t),:])
//   row(t) = venueid2coor[inputs_poi[t]]
// R13: single fused prep kernel (build lists -> grid barrier -> row-sorted
// compact, self-cleaning) + uniform row-sorted stream kernel (L2 dedups
// duplicate-row reads; proven in R12: 373MB traffic @ 5.7TB/s).

#define N_POI    10000
#define V_SIZE   20000
#define N_TOK    6400

#define SEGMENTS 2
#define SEG_VEC  1250        // float4 per segment (2500 total per row)
#define FULL_IT  4           // 4*256 = 1024 vectors
#define TAIL     226         // 1250 - 1024

#define PREP_BLOCKS 40
#define PREP_THREADS 256     // 40*256 = 10240 >= max(N_POI, N_TOK)

// All zero-initialized; every field returns to its initial state each call.
__device__ int g_head[N_POI];    // 0 = empty, else token+1
__device__ int g_next[N_TOK];    // same encoding
__device__ int g_tok[N_TOK];     // tokens in row-sorted order
__device__ int g_row[N_TOK];
__device__ int g_cursor;         // reset by stream kernel
__device__ int g_bar_arrive;     // barrier state, reset by last finisher
__device__ volatile int g_bar_release;
__device__ int g_bar_done;

__global__ void __launch_bounds__(PREP_THREADS) prep_kernel(
    const void* __restrict__ venueid2coor,
    const void* __restrict__ inputs_poi,
    int n_tok)
{
    const int gid = blockIdx.x * PREP_THREADS + threadIdx.x;

    // Per-block dtype detection (LE int64 of small values -> odd words zero).
    __shared__ int s_poi64, s_v2c64;
    if (threadIdx.x == 0) {
        const unsigned int* poi = (const unsigned int*)inputs_poi;
        const unsigned int* v2c = (const unsigned int*)venueid2coor;
        int p = 1, v = 1;
        #pragma unroll
        for (int k = 1; k < 32; k += 2) {
            if (poi[k] != 0u) p = 0;
            if (v2c[k] != 0u) v = 0;
        }
        s_poi64 = p; s_v2c64 = v;
    }
    __syncthreads();
    const int poi64 = s_poi64, v2c64 = s_v2c64;

    // Phase 1: push tokens onto per-row lists (head==0 means empty).
    if (gid < n_tok) {
        long long vid = poi64 ? ((const long long*)inputs_poi)[gid]
                              : (long long)((const int*)inputs_poi)[gid];
        if (vid < 0) vid = 0;
        if (vid >= V_SIZE) vid = V_SIZE - 1;

        long long row = v2c64 ? ((const long long*)venueid2coor)[vid]
                              : (long long)((const int*)venueid2coor)[vid];
        if (row < 0) row = 0;
        if (row >= N_POI) row = N_POI - 1;

        g_next[gid] = atomicExch(&g_head[(int)row], gid + 1);
    }

    // Grid barrier: 40 blocks are always co-resident on 148 SMs.
    __syncthreads();
    if (threadIdx.x == 0) {
        __threadfence();
        if (atomicAdd(&g_bar_arrive, 1) == PREP_BLOCKS - 1)
            g_bar_release = 1;
        while (g_bar_release == 0) { }
    }
    __syncthreads();
    __threadfence();   // acquire all phase-1 writes

    // Phase 2: compact into row-sorted order; self-clean head[] for next call.
    if (gid < N_POI) {
        int v = g_head[gid];
        if (v > 0) {
            int cnt = 0;
            for (int tmp = v; tmp > 0; tmp = g_next[tmp - 1]) cnt++;
            int pos = atomicAdd(&g_cursor, cnt);
            for (int tmp = v; tmp > 0; tmp = g_next[tmp - 1]) {
                g_tok[pos] = tmp - 1;
                g_row[pos] = gid;
                pos++;
            }
            g_head[gid] = 0;
        }
    }

    // Reset barrier state once every block has finished phase 2.
    __syncthreads();
    if (threadIdx.x == 0) {
        __threadfence();
        if (atomicAdd(&g_bar_done, 1) == PREP_BLOCKS - 1) {
            g_bar_arrive = 0;
            g_bar_done = 0;
            g_bar_release = 0;
        }
    }
}

__device__ __forceinline__ float4 xform(float4 v)
{
    const float BIG = 9999999.99f;
    float4 r;
    r.x = __frcp_rn(v.x == 0.0f ? BIG : v.x);
    r.y = __frcp_rn(v.y == 0.0f ? BIG : v.y);
    r.z = __frcp_rn(v.z == 0.0f ? BIG : v.z);
    r.w = __frcp_rn(v.w == 0.0f ? BIG : v.w);
    return r;
}

// grid = (n_tok, SEGMENTS), block = 256. Every CTA does identical work.
__global__ void __launch_bounds__(256) stream_kernel(
    const float* __restrict__ dmat,
    float*       __restrict__ out,
    int n_tok)
{
    const int w = blockIdx.x;
    const int tid = threadIdx.x;

    if (w == 0 && blockIdx.y == 0 && tid == 0)
        g_cursor = 0;                      // reset for next graph replay

    const int row   = g_row[w];            // uniform -> broadcast
    const int token = g_tok[w];
    const int segbase = blockIdx.y * SEG_VEC;

    const float4* __restrict__ src =
        reinterpret_cast<const float4*>(dmat + (size_t)row * N_POI) + segbase;
    float4* __restrict__ dst =
        reinterpret_cast<float4*>(out + (size_t)token * N_POI) + segbase;

    // Caching loads: duplicate-row CTAs are adjacent in bid order -> L2 hits.
    // Streaming stores: output never re-read.
    float4 v[FULL_IT];
    #pragma unroll
    for (int k = 0; k < FULL_IT; k++)
        v[k] = __ldg(&src[tid + k * 256]);
    #pragma unroll
    for (int k = 0; k < FULL_IT; k++)
        __stcs(&dst[tid + k * 256], xform(v[k]));
    if (tid < TAIL) {
        float4 t4 = __ldg(&src[FULL_IT * 256 + tid]);
        __stcs(&dst[FULL_IT * 256 + tid], xform(t4));
    }
}

extern "C" void kernel_launch(void* const* d_in, const int* in_sizes, int n_in,
                              void* d_out, int out_size)
{
    const void*  venueid2coor = d_in[0];
    const void*  inputs_poi   = d_in[1];
    const float* dmat         = (const float*)d_in[2];
    float*       out          = (float*)d_out;

    int n_tok = in_sizes[1];
    if (n_tok > N_TOK) n_tok = N_TOK;

    prep_kernel<<<PREP_BLOCKS, PREP_THREADS>>>(venueid2coor, inputs_poi, n_tok);

    dim3 grid(n_tok, SEGMENTS);
    stream_kernel<<<grid, 256>>>(dmat, out, n_tok);
}